// round 13
// baseline (speedup 1.0000x reference)
#include <cuda_runtime.h>
#include <stdint.h>

// Axial attention over T: 4096 independent [128 x 128] attentions, C=128.
//   n = ((b*H + h)*HH + hh)*WW + ww ; element (t,c) at base(n) + t*32768 + c
#define L 128         // sequence (t) length
#define CD 128        // channel dim
#define PA 132        // smem pitch for Q^T / K^T  (gcd(132,32)=4 -> 4-way transpose-store conflict only)
#define PB 132        // smem pitch for P [t][k] and V [k][c]
#define STRIDE_T 32768
#define NPROB 4096
#define OUT_ELEMS 67108864LL   // B*H*T*HH*WW*C

__device__ __forceinline__ unsigned long long pack2(float x, float y) {
    unsigned long long r;
    asm("mov.b64 %0, {%1, %2};" : "=l"(r)
        : "r"(__float_as_uint(x)), "r"(__float_as_uint(y)));
    return r;
}
__device__ __forceinline__ float2 unpack2(unsigned long long v) {
    unsigned a, b;
    asm("mov.b64 {%0, %1}, %2;" : "=r"(a), "=r"(b) : "l"(v));
    return make_float2(__uint_as_float(a), __uint_as_float(b));
}
// Blackwell packed fp32 FMA (FFMA2) — only reachable via PTX fma.rn.f32x2
__device__ __forceinline__ unsigned long long ffma2(unsigned long long a,
                                                    unsigned long long b,
                                                    unsigned long long c) {
    unsigned long long d;
    asm("fma.rn.f32x2 %0, %1, %2, %3;" : "=l"(d) : "l"(a), "l"(b), "l"(c));
    return d;
}

extern __shared__ float smem[];

__global__ void __launch_bounds__(256, 1)
axial_attn_kernel(const float* __restrict__ Q, const float* __restrict__ K,
                  const float* __restrict__ V, float* __restrict__ Out,
                  float* __restrict__ Attn, int writeAttn)
{
    float* As   = smem;                 // stage1: Q^T [c][t] pitch PA ; stage2: V [k][c] pitch PB
    float* Bs   = smem + CD * PA;       // K^T [c][t(k)] pitch PA
    float* Ps   = smem + 2 * CD * PA;   // scores/probs [t][k] pitch PB
    float* rinv = As + L * PB;          // 128 floats of spare space in the As region (stage2)

    const int tid = threadIdx.x;
    const int n   = blockIdx.x;
    const size_t base = (size_t)(n >> 8) * (size_t)L * STRIDE_T
                      + (size_t)(n & 255) * CD;

    // ---- load Q^T, K^T into smem (coalesced global, 4-way smem transpose store) ----
    for (int idx = tid; idx < L * CD; idx += 256) {
        const int t = idx >> 7, c = idx & 127;
        const size_t g = base + (size_t)t * STRIDE_T + c;
        As[c * PA + t] = Q[g];
        Bs[c * PA + t] = K[g];
    }
    __syncthreads();

    const int tx = tid & 15, ty = tid >> 4;
    const int r0 = ty * 8;   // query rows
    const int c0 = tx * 8;   // key cols (stage1) / channel cols (stage2)

    // ================= S = Q K^T (raw scores) =================
    {
        unsigned long long acc[8][4];
        #pragma unroll
        for (int i = 0; i < 8; i++)
            #pragma unroll
            for (int j = 0; j < 4; j++) acc[i][j] = 0ULL;

        #pragma unroll 2
        for (int c = 0; c < CD; ++c) {
            const float4 q0 = *(const float4*)&As[c * PA + r0];
            const float4 q1 = *(const float4*)&As[c * PA + r0 + 4];
            const ulonglong2 ka = *(const ulonglong2*)&Bs[c * PA + c0];
            const ulonglong2 kb = *(const ulonglong2*)&Bs[c * PA + c0 + 4];
            const unsigned long long kp[4] = {ka.x, ka.y, kb.x, kb.y};
            const float qs[8] = {q0.x, q0.y, q0.z, q0.w, q1.x, q1.y, q1.z, q1.w};
            #pragma unroll
            for (int i = 0; i < 8; i++) {
                const unsigned long long qq = pack2(qs[i], qs[i]);
                #pragma unroll
                for (int j = 0; j < 4; j++)
                    acc[i][j] = ffma2(kp[j], qq, acc[i][j]);
            }
        }
        // write S to Ps[t][k]
        #pragma unroll
        for (int i = 0; i < 8; i++) {
            const float2 a0 = unpack2(acc[i][0]);
            const float2 a1 = unpack2(acc[i][1]);
            const float2 a2 = unpack2(acc[i][2]);
            const float2 a3 = unpack2(acc[i][3]);
            float4 w0 = make_float4(a0.x, a0.y, a1.x, a1.y);
            float4 w1 = make_float4(a2.x, a2.y, a3.x, a3.y);
            *(float4*)&Ps[(r0 + i) * PB + c0]     = w0;
            *(float4*)&Ps[(r0 + i) * PB + c0 + 4] = w1;
        }
    }
    __syncthreads();

    // ========= softmax (threads 0..127)  ||  V load (threads 128..255) =========
    if (tid < 128) {
        const int t = tid;
        float* row = &Ps[t * PB];
        float m = -1e30f;
        #pragma unroll 4
        for (int kk = 0; kk < L; kk += 4) {
            float4 s = *(const float4*)&row[kk];
            m = fmaxf(m, fmaxf(fmaxf(s.x, s.y), fmaxf(s.z, s.w)));
        }
        const float inv_scale = 0.08838834764831845f;  // 1/sqrt(128)
        float sum = 0.f;
        #pragma unroll 4
        for (int kk = 0; kk < L; kk += 4) {
            float4 s = *(const float4*)&row[kk];
            s.x = __expf((s.x - m) * inv_scale);
            s.y = __expf((s.y - m) * inv_scale);
            s.z = __expf((s.z - m) * inv_scale);
            s.w = __expf((s.w - m) * inv_scale);
            sum += (s.x + s.y) + (s.z + s.w);
            *(float4*)&row[kk] = s;   // keep UNNORMALIZED exp; fold 1/sum later
        }
        rinv[t] = 1.0f / sum;
    } else {
        // load V (natural [k][c] layout) into the dead Q^T region
        const int c = tid - 128;
        #pragma unroll 4
        for (int kk = 0; kk < L; kk++) {
            As[kk * PB + c] = V[base + (size_t)kk * STRIDE_T + c];
        }
    }
    __syncthreads();

    // optional attn output (normalized on the fly)
    if (writeAttn) {
        float* attn_n = Attn + (size_t)n * (L * L);
        for (int idx = tid; idx < L * L; idx += 256) {
            const int t = idx >> 7, kk = idx & 127;
            attn_n[idx] = Ps[t * PB + kk] * rinv[t];
        }
    }

    // ================= O = P V (normalize in epilogue) =================
    {
        unsigned long long acc[8][4];
        #pragma unroll
        for (int i = 0; i < 8; i++)
            #pragma unroll
            for (int j = 0; j < 4; j++) acc[i][j] = 0ULL;

        #pragma unroll 2
        for (int kk = 0; kk < L; ++kk) {
            const ulonglong2 va = *(const ulonglong2*)&As[kk * PB + c0];
            const ulonglong2 vb = *(const ulonglong2*)&As[kk * PB + c0 + 4];
            const unsigned long long vp[4] = {va.x, va.y, vb.x, vb.y};
            #pragma unroll
            for (int i = 0; i < 8; i++) {
                const float p = Ps[(r0 + i) * PB + kk];   // broadcast LDS
                const unsigned long long pp = pack2(p, p);
                #pragma unroll
                for (int j = 0; j < 4; j++)
                    acc[i][j] = ffma2(vp[j], pp, acc[i][j]);
            }
        }

        #pragma unroll
        for (int i = 0; i < 8; i++) {
            const float r = rinv[r0 + i];
            const float2 a0 = unpack2(acc[i][0]);
            const float2 a1 = unpack2(acc[i][1]);
            const float2 a2 = unpack2(acc[i][2]);
            const float2 a3 = unpack2(acc[i][3]);
            float4 w0 = make_float4(a0.x * r, a0.y * r, a1.x * r, a1.y * r);
            float4 w1 = make_float4(a2.x * r, a2.y * r, a3.x * r, a3.y * r);
            const size_t g = base + (size_t)(r0 + i) * STRIDE_T + c0;
            *(float4*)&Out[g]     = w0;
            *(float4*)&Out[g + 4] = w1;
        }
    }
}

extern "C" void kernel_launch(void* const* d_in, const int* in_sizes, int n_in,
                              void* d_out, int out_size) {
    const float* q = (const float*)d_in[0];
    const float* k = (const float*)d_in[1];
    const float* v = (const float*)d_in[2];
    float* out = (float*)d_out;

    // Reference returns (out, attn); if the flattened output covers both, write both.
    const int writeAttn = ((long long)out_size >= 2LL * OUT_ELEMS) ? 1 : 0;
    float* attn = out + OUT_ELEMS;

    const size_t smem_bytes = (size_t)(2 * CD * PA + L * PB) * sizeof(float); // 215040
    cudaFuncSetAttribute(axial_attn_kernel,
                         cudaFuncAttributeMaxDynamicSharedMemorySize,
                         (int)smem_bytes);

    axial_attn_kernel<<<NPROB, 256, smem_bytes>>>(q, k, v, out, attn, writeAttn);
}

// round 15
// speedup vs baseline: 2.5684x; 2.5684x over previous
#include <cuda_runtime.h>
#include <cuda_bf16.h>
#include <stdint.h>

// Axial attention over T: 4096 independent [128 x 128] attentions, C=128.
// mma.sync (HMMA) bf16 split-precision (hi+lo, 3 MMAs) — no sm_103a features.

#define L 128
#define CD 128
#define STRIDE_T 32768
#define NPROB 4096
#define OUT_ELEMS 67108864LL

#define ROWB 272                 // padded row: 136 bf16 = 272 B (17 x 16B -> ldmatrix conflict-free)
#define TILEB (128 * ROWB)       // 34816 B per tile
#define QH_OFF 0
#define QL_OFF (1 * TILEB)
#define KH_OFF (2 * TILEB)
#define KL_OFF (3 * TILEB)
#define VH_OFF (4 * TILEB)
#define VL_OFF (5 * TILEB)
#define SMEM_TOTAL (6 * TILEB)   // 208896 B

__device__ __forceinline__ uint32_t smem_u32(const void* p) {
    uint32_t a;
    asm("{ .reg .u64 t; cvta.to.shared.u64 t, %1; cvt.u32.u64 %0, t; }"
        : "=r"(a) : "l"(p));
    return a;
}
// split fp32 pair (x -> lower bf16, y -> upper bf16) into hi + residual-lo words
__device__ __forceinline__ void split2(float x, float y, uint32_t& hi, uint32_t& lo) {
    uint32_t h;
    asm("cvt.rn.bf16x2.f32 %0, %1, %2;" : "=r"(h) : "f"(y), "f"(x));
    float hx = __uint_as_float(h << 16);
    float hy = __uint_as_float(h & 0xffff0000u);
    float rx = x - hx, ry = y - hy;
    asm("cvt.rn.bf16x2.f32 %0, %1, %2;" : "=r"(lo) : "f"(ry), "f"(rx));
    hi = h;
}
__device__ __forceinline__ void ldsm4(uint32_t* r, uint32_t addr) {
    asm volatile("ldmatrix.sync.aligned.m8n8.x4.shared.b16 {%0,%1,%2,%3}, [%4];"
                 : "=r"(r[0]), "=r"(r[1]), "=r"(r[2]), "=r"(r[3]) : "r"(addr));
}
__device__ __forceinline__ void mma16816(float* d, const uint32_t* a,
                                         uint32_t b0, uint32_t b1) {
    asm volatile("mma.sync.aligned.m16n8k16.row.col.f32.bf16.bf16.f32 "
                 "{%0,%1,%2,%3}, {%4,%5,%6,%7}, {%8,%9}, {%0,%1,%2,%3};"
                 : "+f"(d[0]), "+f"(d[1]), "+f"(d[2]), "+f"(d[3])
                 : "r"(a[0]), "r"(a[1]), "r"(a[2]), "r"(a[3]), "r"(b0), "r"(b1));
}

extern __shared__ char smem[];

__global__ void __launch_bounds__(256, 1)
axial_attn_hmma(const float* __restrict__ Q, const float* __restrict__ K,
                const float* __restrict__ V, float* __restrict__ Out,
                float* __restrict__ Attn, int writeAttn)
{
    char* sm = smem;
    const uint32_t sb = smem_u32(smem);
    const int tid = threadIdx.x, wid = tid >> 5, lane = tid & 31;
    const int n = blockIdx.x;
    const size_t base = (size_t)(n >> 8) * (size_t)L * STRIDE_T
                      + (size_t)(n & 255) * CD;

    // ======== phase 1: load Q,K (natural rows) + V (transposed) as split-bf16 ========
    #pragma unroll 4
    for (int i = tid; i < 4096; i += 256) {
        const int row = i >> 5, c4 = (i & 31) << 2;
        const size_t g = base + (size_t)row * STRIDE_T + c4;
        const float4 qv = *(const float4*)(Q + g);
        const float4 kv = *(const float4*)(K + g);
        const uint32_t off = (uint32_t)row * ROWB + (uint32_t)c4 * 2;
        uint32_t h0, l0, h1, l1;
        split2(qv.x, qv.y, h0, l0); split2(qv.z, qv.w, h1, l1);
        *(uint64_t*)(sm + QH_OFF + off) = ((uint64_t)h1 << 32) | h0;
        *(uint64_t*)(sm + QL_OFF + off) = ((uint64_t)l1 << 32) | l0;
        split2(kv.x, kv.y, h0, l0); split2(kv.z, kv.w, h1, l1);
        *(uint64_t*)(sm + KH_OFF + off) = ((uint64_t)h1 << 32) | h0;
        *(uint64_t*)(sm + KL_OFF + off) = ((uint64_t)l1 << 32) | l0;
    }
    {   // V^T[c][k]: coalesced gmem reads (c = lane), transpose into smem rows c
        const int c  = (wid & 3) * 32 + lane;
        const int k0 = (wid >> 2) * 64;
        #pragma unroll 4
        for (int k2 = 0; k2 < 32; ++k2) {
            const int kk = k0 + 2 * k2;
            const float v0 = V[base + (size_t)kk * STRIDE_T + c];
            const float v1 = V[base + (size_t)(kk + 1) * STRIDE_T + c];
            uint32_t h, l; split2(v0, v1, h, l);
            const uint32_t off = (uint32_t)c * ROWB + (uint32_t)kk * 2;
            *(uint32_t*)(sm + VH_OFF + off) = h;
            *(uint32_t*)(sm + VL_OFF + off) = l;
        }
    }
    __syncthreads();

    // fragment addressing: lanes 0-15 -> rows (chunk 0), 16-31 -> rows (chunk 1)
    const int rsel = lane & 15, csel = lane >> 4;
    const uint32_t aAddrBase = sb + QH_OFF + (uint32_t)(16 * wid + rsel) * ROWB + csel * 16;
    const uint32_t bAddrQK   = sb + KH_OFF + (uint32_t)rsel * ROWB + csel * 16;
    const uint32_t bAddrPV   = sb + VH_OFF + (uint32_t)rsel * ROWB + csel * 16;

    float acc[16][4];
    #pragma unroll
    for (int j = 0; j < 16; j++) { acc[j][0] = acc[j][1] = acc[j][2] = acc[j][3] = 0.f; }

    // ======== GEMM1: S = Q K^T  (warp w -> rows 16w..16w+15, fp32 accum) ========
    #pragma unroll 2
    for (int ks = 0; ks < 8; ++ks) {
        uint32_t aH[4], aL[4];
        const uint32_t aAddr = aAddrBase + ks * 32;
        ldsm4(aH, aAddr);
        ldsm4(aL, aAddr + TILEB);
        #pragma unroll
        for (int ng = 0; ng < 8; ++ng) {
            uint32_t bH[4], bL[4];
            const uint32_t bAddr = bAddrQK + (uint32_t)ng * (16 * ROWB) + ks * 32;
            ldsm4(bH, bAddr);
            ldsm4(bL, bAddr + TILEB);
            mma16816(acc[2*ng],     aH, bH[0], bH[2]);
            mma16816(acc[2*ng],     aH, bL[0], bL[2]);
            mma16816(acc[2*ng],     aL, bH[0], bH[2]);
            mma16816(acc[2*ng + 1], aH, bH[1], bH[3]);
            mma16816(acc[2*ng + 1], aH, bL[1], bL[3]);
            mma16816(acc[2*ng + 1], aL, bH[1], bH[3]);
        }
    }

    // ======== softmax in registers (rows q0 = 16w + lane/4, q1 = q0+8) ========
    const int r = lane >> 2, cq = lane & 3;
    const int q0 = 16 * wid + r, q1 = q0 + 8;
    float m0 = -1e30f, m1 = -1e30f;
    #pragma unroll
    for (int j = 0; j < 16; j++) {
        m0 = fmaxf(m0, fmaxf(acc[j][0], acc[j][1]));
        m1 = fmaxf(m1, fmaxf(acc[j][2], acc[j][3]));
    }
    m0 = fmaxf(m0, __shfl_xor_sync(0xffffffffu, m0, 1));
    m0 = fmaxf(m0, __shfl_xor_sync(0xffffffffu, m0, 2));
    m1 = fmaxf(m1, __shfl_xor_sync(0xffffffffu, m1, 1));
    m1 = fmaxf(m1, __shfl_xor_sync(0xffffffffu, m1, 2));
    const float is = 0.08838834764831845f;   // 1/sqrt(128)
    float s0 = 0.f, s1 = 0.f;
    #pragma unroll
    for (int j = 0; j < 16; j++) {
        acc[j][0] = __expf((acc[j][0] - m0) * is);
        acc[j][1] = __expf((acc[j][1] - m0) * is);
        acc[j][2] = __expf((acc[j][2] - m1) * is);
        acc[j][3] = __expf((acc[j][3] - m1) * is);
        s0 += acc[j][0] + acc[j][1];
        s1 += acc[j][2] + acc[j][3];
    }
    s0 += __shfl_xor_sync(0xffffffffu, s0, 1);
    s0 += __shfl_xor_sync(0xffffffffu, s0, 2);
    s1 += __shfl_xor_sync(0xffffffffu, s1, 1);
    s1 += __shfl_xor_sync(0xffffffffu, s1, 2);
    const float rv0 = 1.0f / s0, rv1 = 1.0f / s1;

    // unnormalized P -> split-bf16 into the (dead) Q tiles; warp touches only its own rows
    #pragma unroll
    for (int j = 0; j < 16; j++) {
        const uint32_t off = (uint32_t)(8 * j + 2 * cq) * 2;
        uint32_t h, l;
        split2(acc[j][0], acc[j][1], h, l);
        *(uint32_t*)(sm + QH_OFF + (uint32_t)q0 * ROWB + off) = h;
        *(uint32_t*)(sm + QL_OFF + (uint32_t)q0 * ROWB + off) = l;
        split2(acc[j][2], acc[j][3], h, l);
        *(uint32_t*)(sm + QH_OFF + (uint32_t)q1 * ROWB + off) = h;
        *(uint32_t*)(sm + QL_OFF + (uint32_t)q1 * ROWB + off) = l;
    }
    if (writeAttn) {   // normalized attn from fp32 values (pre-quantization)
        float* a0 = Attn + (size_t)n * (L * L) + (size_t)q0 * L;
        float* a1 = Attn + (size_t)n * (L * L) + (size_t)q1 * L;
        #pragma unroll
        for (int j = 0; j < 16; j++) {
            const int col = 8 * j + 2 * cq;
            *(float2*)(a0 + col) = make_float2(acc[j][0] * rv0, acc[j][1] * rv0);
            *(float2*)(a1 + col) = make_float2(acc[j][2] * rv1, acc[j][3] * rv1);
        }
    }
    __syncthreads();

    // ======== GEMM2: O = P V (normalize in epilogue) ========
    #pragma unroll
    for (int j = 0; j < 16; j++) { acc[j][0] = acc[j][1] = acc[j][2] = acc[j][3] = 0.f; }
    #pragma unroll 2
    for (int ks = 0; ks < 8; ++ks) {
        uint32_t aH[4], aL[4];
        const uint32_t aAddr = aAddrBase + ks * 32;
        ldsm4(aH, aAddr);
        ldsm4(aL, aAddr + TILEB);
        #pragma unroll
        for (int ng = 0; ng < 8; ++ng) {
            uint32_t bH[4], bL[4];
            const uint32_t bAddr = bAddrPV + (uint32_t)ng * (16 * ROWB) + ks * 32;
            ldsm4(bH, bAddr);
            ldsm4(bL, bAddr + TILEB);
            mma16816(acc[2*ng],     aH, bH[0], bH[2]);
            mma16816(acc[2*ng],     aH, bL[0], bL[2]);
            mma16816(acc[2*ng],     aL, bH[0], bH[2]);
            mma16816(acc[2*ng + 1], aH, bH[1], bH[3]);
            mma16816(acc[2*ng + 1], aH, bL[1], bL[3]);
            mma16816(acc[2*ng + 1], aL, bH[1], bH[3]);
        }
    }

    // ======== epilogue: normalize rows, store O ========
    {
        float* o0 = Out + base + (size_t)q0 * STRIDE_T;
        float* o1 = Out + base + (size_t)q1 * STRIDE_T;
        #pragma unroll
        for (int j = 0; j < 16; j++) {
            const int col = 8 * j + 2 * cq;
            *(float2*)(o0 + col) = make_float2(acc[j][0] * rv0, acc[j][1] * rv0);
            *(float2*)(o1 + col) = make_float2(acc[j][2] * rv1, acc[j][3] * rv1);
        }
    }
}

extern "C" void kernel_launch(void* const* d_in, const int* in_sizes, int n_in,
                              void* d_out, int out_size) {
    const float* q = (const float*)d_in[0];
    const float* k = (const float*)d_in[1];
    const float* v = (const float*)d_in[2];
    float* out = (float*)d_out;

    const int writeAttn = ((long long)out_size >= 2LL * OUT_ELEMS) ? 1 : 0;
    float* attn = out + OUT_ELEMS;

    cudaFuncSetAttribute(axial_attn_hmma,
                         cudaFuncAttributeMaxDynamicSharedMemorySize, SMEM_TOTAL);
    axial_attn_hmma<<<NPROB, 256, SMEM_TOTAL>>>(q, k, v, out, attn, writeAttn);
}

// round 16
// speedup vs baseline: 2.9145x; 1.1348x over previous
#include <cuda_runtime.h>
#include <cuda_bf16.h>
#include <stdint.h>

// Axial attention over T: 4096 independent [128 x 128] attentions, C=128.
// mma.sync (HMMA) bf16 split-precision (hi+lo, 3 MMAs), 512 threads/CTA,
// warp pair splits N: warp (g, nhalf) = rows 16g..16g+15, cols 64*nhalf..+63.

#define L 128
#define CD 128
#define STRIDE_T 32768
#define NPROB 4096
#define OUT_ELEMS 67108864LL

#define ROWB 272                 // padded row: 136 bf16 = 272 B (17 x 16B chunks)
#define TILEB (128 * ROWB)       // 34816 B per tile
#define SM_RED 0                 // pmax[2][128], psum[2][128] floats = 2048 B
#define SM_TILE0 2048
#define QH_OFF (SM_TILE0 + 0 * TILEB)
#define QL_OFF (SM_TILE0 + 1 * TILEB)
#define KH_OFF (SM_TILE0 + 2 * TILEB)
#define KL_OFF (SM_TILE0 + 3 * TILEB)
#define VH_OFF (SM_TILE0 + 4 * TILEB)
#define VL_OFF (SM_TILE0 + 5 * TILEB)
#define SMEM_TOTAL (SM_TILE0 + 6 * TILEB)   // 210944 B

__device__ __forceinline__ uint32_t smem_u32(const void* p) {
    uint32_t a;
    asm("{ .reg .u64 t; cvta.to.shared.u64 t, %1; cvt.u32.u64 %0, t; }"
        : "=r"(a) : "l"(p));
    return a;
}
// split fp32 pair (x -> lower bf16, y -> upper bf16) into hi + residual-lo words
__device__ __forceinline__ void split2(float x, float y, uint32_t& hi, uint32_t& lo) {
    uint32_t h;
    asm("cvt.rn.bf16x2.f32 %0, %1, %2;" : "=r"(h) : "f"(y), "f"(x));
    float hx = __uint_as_float(h << 16);
    float hy = __uint_as_float(h & 0xffff0000u);
    float rx = x - hx, ry = y - hy;
    asm("cvt.rn.bf16x2.f32 %0, %1, %2;" : "=r"(lo) : "f"(ry), "f"(rx));
    hi = h;
}
__device__ __forceinline__ void ldsm4(uint32_t* r, uint32_t addr) {
    asm volatile("ldmatrix.sync.aligned.m8n8.x4.shared.b16 {%0,%1,%2,%3}, [%4];"
                 : "=r"(r[0]), "=r"(r[1]), "=r"(r[2]), "=r"(r[3]) : "r"(addr));
}
__device__ __forceinline__ void mma16816(float* d, const uint32_t* a,
                                         uint32_t b0, uint32_t b1) {
    asm volatile("mma.sync.aligned.m16n8k16.row.col.f32.bf16.bf16.f32 "
                 "{%0,%1,%2,%3}, {%4,%5,%6,%7}, {%8,%9}, {%0,%1,%2,%3};"
                 : "+f"(d[0]), "+f"(d[1]), "+f"(d[2]), "+f"(d[3])
                 : "r"(a[0]), "r"(a[1]), "r"(a[2]), "r"(a[3]), "r"(b0), "r"(b1));
}

extern __shared__ char smem[];

__global__ void __launch_bounds__(512, 1)
axial_attn_hmma(const float* __restrict__ Q, const float* __restrict__ K,
                const float* __restrict__ V, float* __restrict__ Out,
                float* __restrict__ Attn, int writeAttn)
{
    char* sm = smem;
    const uint32_t sb = smem_u32(smem);
    const int tid = threadIdx.x, wid = tid >> 5, lane = tid & 31;
    const int n = blockIdx.x;
    const size_t base = (size_t)(n >> 8) * (size_t)L * STRIDE_T
                      + (size_t)(n & 255) * CD;

    float* pmax = (float*)(sm + SM_RED);         // [2][128]
    float* psum = pmax + 256;                    // [2][128]

    // ======== phase 1: load Q,K (natural rows) + V (transposed) as split-bf16 ========
    #pragma unroll 4
    for (int i = tid; i < 4096; i += 512) {
        const int row = i >> 5, c4 = (i & 31) << 2;
        const size_t g = base + (size_t)row * STRIDE_T + c4;
        const float4 qv = *(const float4*)(Q + g);
        const float4 kv = *(const float4*)(K + g);
        const uint32_t off = (uint32_t)row * ROWB + (uint32_t)c4 * 2;
        uint32_t h0, l0, h1, l1;
        split2(qv.x, qv.y, h0, l0); split2(qv.z, qv.w, h1, l1);
        *(uint64_t*)(sm + QH_OFF + off) = ((uint64_t)h1 << 32) | h0;
        *(uint64_t*)(sm + QL_OFF + off) = ((uint64_t)l1 << 32) | l0;
        split2(kv.x, kv.y, h0, l0); split2(kv.z, kv.w, h1, l1);
        *(uint64_t*)(sm + KH_OFF + off) = ((uint64_t)h1 << 32) | h0;
        *(uint64_t*)(sm + KL_OFF + off) = ((uint64_t)l1 << 32) | l0;
    }
    {   // V^T[c][k]: coalesced gmem reads (c = lane-contig), transpose into smem rows c
        const int c  = (wid & 3) * 32 + lane;
        const int k0 = (wid >> 2) * 32;
        #pragma unroll 4
        for (int k2 = 0; k2 < 16; ++k2) {
            const int kk = k0 + 2 * k2;
            const float v0 = V[base + (size_t)kk * STRIDE_T + c];
            const float v1 = V[base + (size_t)(kk + 1) * STRIDE_T + c];
            uint32_t h, l; split2(v0, v1, h, l);
            const uint32_t off = (uint32_t)c * ROWB + (uint32_t)kk * 2;
            *(uint32_t*)(sm + VH_OFF + off) = h;
            *(uint32_t*)(sm + VL_OFF + off) = l;
        }
    }
    __syncthreads();

    // warp mapping: g = row group (16 rows), nhalf = column half (64 cols)
    const int g_ = wid >> 1, nhalf = wid & 1;
    const int rsel = lane & 15, csel = lane >> 4;
    const uint32_t aAddrBase = sb + QH_OFF + (uint32_t)(16 * g_ + rsel) * ROWB + csel * 16;
    const uint32_t bAddrQK = sb + KH_OFF + (uint32_t)(64 * nhalf + rsel) * ROWB + csel * 16;
    const uint32_t bAddrPV = sb + VH_OFF + (uint32_t)(64 * nhalf + rsel) * ROWB + csel * 16;

    float acc[8][4];
    #pragma unroll
    for (int j = 0; j < 8; j++) { acc[j][0] = acc[j][1] = acc[j][2] = acc[j][3] = 0.f; }

    // ======== GEMM1: S = Q K^T  (rows 16g.., cols 64*nhalf.., fp32 accum) ========
    #pragma unroll
    for (int ks = 0; ks < 8; ++ks) {
        uint32_t aH[4], aL[4];
        const uint32_t aAddr = aAddrBase + ks * 32;
        ldsm4(aH, aAddr);
        ldsm4(aL, aAddr + TILEB);
        #pragma unroll
        for (int ng = 0; ng < 4; ++ng) {
            uint32_t bH[4], bL[4];
            const uint32_t bAddr = bAddrQK + (uint32_t)ng * (16 * ROWB) + ks * 32;
            ldsm4(bH, bAddr);
            ldsm4(bL, bAddr + TILEB);
            mma16816(acc[2*ng],     aH, bH[0], bH[2]);
            mma16816(acc[2*ng],     aH, bL[0], bL[2]);
            mma16816(acc[2*ng],     aL, bH[0], bH[2]);
            mma16816(acc[2*ng + 1], aH, bH[1], bH[3]);
            mma16816(acc[2*ng + 1], aH, bL[1], bL[3]);
            mma16816(acc[2*ng + 1], aL, bH[1], bH[3]);
        }
    }

    // ======== softmax: intra-warp over 64 cols, cross-half via smem ========
    const int r = lane >> 2, cq = lane & 3;
    const int q0 = 16 * g_ + r, q1 = q0 + 8;
    float m0 = -1e30f, m1 = -1e30f;
    #pragma unroll
    for (int j = 0; j < 8; j++) {
        m0 = fmaxf(m0, fmaxf(acc[j][0], acc[j][1]));
        m1 = fmaxf(m1, fmaxf(acc[j][2], acc[j][3]));
    }
    m0 = fmaxf(m0, __shfl_xor_sync(0xffffffffu, m0, 1));
    m0 = fmaxf(m0, __shfl_xor_sync(0xffffffffu, m0, 2));
    m1 = fmaxf(m1, __shfl_xor_sync(0xffffffffu, m1, 1));
    m1 = fmaxf(m1, __shfl_xor_sync(0xffffffffu, m1, 2));
    if (cq == 0) {
        pmax[nhalf * 128 + q0] = m0;
        pmax[nhalf * 128 + q1] = m1;
    }
    __syncthreads();
    m0 = fmaxf(pmax[q0], pmax[128 + q0]);
    m1 = fmaxf(pmax[q1], pmax[128 + q1]);

    const float is = 0.08838834764831845f;   // 1/sqrt(128)
    float s0 = 0.f, s1 = 0.f;
    #pragma unroll
    for (int j = 0; j < 8; j++) {
        acc[j][0] = __expf((acc[j][0] - m0) * is);
        acc[j][1] = __expf((acc[j][1] - m0) * is);
        acc[j][2] = __expf((acc[j][2] - m1) * is);
        acc[j][3] = __expf((acc[j][3] - m1) * is);
        s0 += acc[j][0] + acc[j][1];
        s1 += acc[j][2] + acc[j][3];
    }
    // unnormalized P -> split-bf16 into the (dead) Q tiles (own rows/cols only)
    #pragma unroll
    for (int j = 0; j < 8; j++) {
        const uint32_t off = (uint32_t)(64 * nhalf + 8 * j + 2 * cq) * 2;
        uint32_t h, l;
        split2(acc[j][0], acc[j][1], h, l);
        *(uint32_t*)(sm + QH_OFF + (uint32_t)q0 * ROWB + off) = h;
        *(uint32_t*)(sm + QL_OFF + (uint32_t)q0 * ROWB + off) = l;
        split2(acc[j][2], acc[j][3], h, l);
        *(uint32_t*)(sm + QH_OFF + (uint32_t)q1 * ROWB + off) = h;
        *(uint32_t*)(sm + QL_OFF + (uint32_t)q1 * ROWB + off) = l;
    }
    s0 += __shfl_xor_sync(0xffffffffu, s0, 1);
    s0 += __shfl_xor_sync(0xffffffffu, s0, 2);
    s1 += __shfl_xor_sync(0xffffffffu, s1, 1);
    s1 += __shfl_xor_sync(0xffffffffu, s1, 2);
    if (cq == 0) {
        psum[nhalf * 128 + q0] = s0;
        psum[nhalf * 128 + q1] = s1;
    }
    __syncthreads();   // guards psum AND the P tile stores for GEMM2
    const float rv0 = 1.0f / (psum[q0] + psum[128 + q0]);
    const float rv1 = 1.0f / (psum[q1] + psum[128 + q1]);

    if (writeAttn) {   // normalized attn from fp32 values (pre-quantization)
        float* a0 = Attn + (size_t)n * (L * L) + (size_t)q0 * L + 64 * nhalf;
        float* a1 = Attn + (size_t)n * (L * L) + (size_t)q1 * L + 64 * nhalf;
        #pragma unroll
        for (int j = 0; j < 8; j++) {
            const int col = 8 * j + 2 * cq;
            *(float2*)(a0 + col) = make_float2(acc[j][0] * rv0, acc[j][1] * rv0);
            *(float2*)(a1 + col) = make_float2(acc[j][2] * rv1, acc[j][3] * rv1);
        }
    }

    // ======== GEMM2: O = P V (normalize in epilogue) ========
    #pragma unroll
    for (int j = 0; j < 8; j++) { acc[j][0] = acc[j][1] = acc[j][2] = acc[j][3] = 0.f; }
    #pragma unroll
    for (int ks = 0; ks < 8; ++ks) {
        uint32_t aH[4], aL[4];
        const uint32_t aAddr = aAddrBase + ks * 32;
        ldsm4(aH, aAddr);
        ldsm4(aL, aAddr + TILEB);
        #pragma unroll
        for (int ng = 0; ng < 4; ++ng) {
            uint32_t bH[4], bL[4];
            const uint32_t bAddr = bAddrPV + (uint32_t)ng * (16 * ROWB) + ks * 32;
            ldsm4(bH, bAddr);
            ldsm4(bL, bAddr + TILEB);
            mma16816(acc[2*ng],     aH, bH[0], bH[2]);
            mma16816(acc[2*ng],     aH, bL[0], bL[2]);
            mma16816(acc[2*ng],     aL, bH[0], bH[2]);
            mma16816(acc[2*ng + 1], aH, bH[1], bH[3]);
            mma16816(acc[2*ng + 1], aH, bL[1], bL[3]);
            mma16816(acc[2*ng + 1], aL, bH[1], bH[3]);
        }
    }

    // ======== epilogue: normalize rows, store O ========
    {
        float* o0 = Out + base + (size_t)q0 * STRIDE_T + 64 * nhalf;
        float* o1 = Out + base + (size_t)q1 * STRIDE_T + 64 * nhalf;
        #pragma unroll
        for (int j = 0; j < 8; j++) {
            const int col = 8 * j + 2 * cq;
            *(float2*)(o0 + col) = make_float2(acc[j][0] * rv0, acc[j][1] * rv0);
            *(float2*)(o1 + col) = make_float2(acc[j][2] * rv1, acc[j][3] * rv1);
        }
    }
}

extern "C" void kernel_launch(void* const* d_in, const int* in_sizes, int n_in,
                              void* d_out, int out_size) {
    const float* q = (const float*)d_in[0];
    const float* k = (const float*)d_in[1];
    const float* v = (const float*)d_in[2];
    float* out = (float*)d_out;

    const int writeAttn = ((long long)out_size >= 2LL * OUT_ELEMS) ? 1 : 0;
    float* attn = out + OUT_ELEMS;

    cudaFuncSetAttribute(axial_attn_hmma,
                         cudaFuncAttributeMaxDynamicSharedMemorySize, SMEM_TOTAL);
    axial_attn_hmma<<<NPROB, 512, SMEM_TOTAL>>>(q, k, v, out, attn, writeAttn);
}